// round 1
// baseline (speedup 1.0000x reference)
#include <cuda_runtime.h>
#include <math_constants.h>

// Problem constants
#define BB 4
#define QL 1024
#define KLEN 1024
#define CC 256
#define HH 8
#define DD 32
#define MM (BB * QL)  // 4096 rows in all projection GEMMs

// Scratch (device globals: no allocation allowed)
__device__ float g_qp[MM * CC];  // q / sqrt(D), layout [b*Q + q][h*D + d]
__device__ float g_kp[MM * CC];  // k
__device__ float g_vp[MM * CC];  // v
__device__ float g_gp[MM * CC];  // sigmoid(q_x @ wg^T + bg)
__device__ float g_o [MM * CC];  // gated attention output (input to final GEMM)

// ---------------------------------------------------------------------------
// Generic GEMM: Y[m][n] = sum_k X[m][k] * W[n][k]  (M=4096, N=256, K=256)
// mode 0: Y=g_qp, X=q_x,  W=wq, epilogue *= 1/sqrt(32)
// mode 1: Y=g_kp, X=kv_x, W=wk
// mode 2: Y=g_vp, X=kv_x, W=wv
// mode 3: Y=g_gp, X=q_x,  W=wg, epilogue sigmoid(v + bg[n])
// mode 4: Y=out,  X=g_o,  W=wo, epilogue v + bo[n]
// Tiles: BM=BN=64, BK=16, 256 threads, 4x4 microtile per thread.
// ---------------------------------------------------------------------------
__global__ __launch_bounds__(256)
void gemm_kernel(const float* __restrict__ qx, const float* __restrict__ kvx,
                 const float* __restrict__ wq, const float* __restrict__ wk,
                 const float* __restrict__ wv, const float* __restrict__ wg,
                 const float* __restrict__ bg, const float* __restrict__ wo,
                 const float* __restrict__ bo, float* __restrict__ outp,
                 int mode_base)
{
    __shared__ __align__(16) float Xs[16][68];  // [k][m], stride 68 keeps float4 16B-aligned
    __shared__ __align__(16) float Ws[16][68];  // [k][n]

    const int mode = mode_base + blockIdx.z;
    const float* X;
    const float* W;
    const float* bias = nullptr;
    float* Y;
    switch (mode) {
        case 0:  X = qx;   W = wq; Y = g_qp; break;
        case 1:  X = kvx;  W = wk; Y = g_kp; break;
        case 2:  X = kvx;  W = wv; Y = g_vp; break;
        case 3:  X = qx;   W = wg; Y = g_gp; bias = bg; break;
        default: X = g_o;  W = wo; Y = outp; bias = bo; break;
    }

    const int tid = threadIdx.x;
    const int tx = tid & 15;        // 0..15 -> 4 output cols
    const int ty = tid >> 4;        // 0..15 -> 4 output rows
    const int m0 = blockIdx.y * 64;
    const int n0 = blockIdx.x * 64;

    float acc[4][4] = {};

    for (int kk = 0; kk < CC; kk += 16) {
        // Load 64x16 tiles of X and W, transposed into [k][m] layout.
        #pragma unroll
        for (int i = 0; i < 4; i++) {
            int e = tid + i * 256;
            int m = e >> 4;
            int k = e & 15;
            Xs[k][m] = X[(size_t)(m0 + m) * CC + kk + k];
            Ws[k][m] = W[(size_t)(n0 + m) * CC + kk + k];
        }
        __syncthreads();

        #pragma unroll
        for (int k = 0; k < 16; k++) {
            float4 a4 = *(const float4*)&Xs[k][ty * 4];
            float4 b4 = *(const float4*)&Ws[k][tx * 4];
            float av[4] = {a4.x, a4.y, a4.z, a4.w};
            float bv[4] = {b4.x, b4.y, b4.z, b4.w};
            #pragma unroll
            for (int i = 0; i < 4; i++)
                #pragma unroll
                for (int j = 0; j < 4; j++)
                    acc[i][j] = fmaf(av[i], bv[j], acc[i][j]);
        }
        __syncthreads();
    }

    #pragma unroll
    for (int i = 0; i < 4; i++) {
        int m = m0 + ty * 4 + i;
        #pragma unroll
        for (int j = 0; j < 4; j++) {
            int n = n0 + tx * 4 + j;
            float v = acc[i][j];
            if (mode == 0) {
                v *= 0.17677669529663689f;  // 1/sqrt(32)
            } else if (mode == 3) {
                v = 1.0f / (1.0f + __expf(-(v + bias[n])));
            } else if (mode == 4) {
                v += bias[n];
            }
            acc[i][j] = v;
        }
        *(float4*)&Y[(size_t)m * CC + n0 + tx * 4] =
            make_float4(acc[i][0], acc[i][1], acc[i][2], acc[i][3]);
    }
}

// ---------------------------------------------------------------------------
// Fused flash attention + gating.
// Grid: (Q/64, H, B). Block: 256 threads (16x16 microtile grid).
// Per block: one 64-query tile of one (b,h); loop over 16 key tiles of 64.
// s = q·k^T + mask_bias + pair_bias; online softmax; o += p·v; o *= gate/l.
// ---------------------------------------------------------------------------
__global__ __launch_bounds__(256)
void attn_kernel(const float* __restrict__ mask_bias,
                 const float* __restrict__ pair_bias)
{
    __shared__ __align__(16) float qs [32][64];   // [d][row]
    __shared__ __align__(16) float kts[32][64];   // [d][key]
    __shared__ __align__(16) float vs [64][32];   // [key][d]
    __shared__ __align__(16) float ps [64][64];   // probs [row][key]
    __shared__ float m_sh[64], l_sh[64], f_sh[64];

    const int tid = threadIdx.x;
    const int tx = tid & 15;   // score phase: 4 keys; AV phase: 2 dims
    const int ty = tid >> 4;   // 4 rows
    const int q0 = blockIdx.x * 64;
    const int h  = blockIdx.y;
    const int b  = blockIdx.z;

    // Load q tile (transposed to d-major). Coalesced: 8 lanes x 16B per row.
    #pragma unroll
    for (int pass = 0; pass < 2; pass++) {
        int r  = (tid >> 3) + pass * 32;
        int dg = (tid & 7) * 4;
        float4 x = *(const float4*)(g_qp + (size_t)(b * QL + q0 + r) * CC + h * DD + dg);
        qs[dg + 0][r] = x.x; qs[dg + 1][r] = x.y;
        qs[dg + 2][r] = x.z; qs[dg + 3][r] = x.w;
    }
    if (tid < 64) { m_sh[tid] = -CUDART_INF_F; l_sh[tid] = 0.0f; }

    float o[4][2] = {};  // rows ty*4+i, dims tx*2+jj

    for (int kt = 0; kt < 16; kt++) {
        const int k0 = kt * 64;

        // Load k (transposed) and v (natural) tiles.
        #pragma unroll
        for (int pass = 0; pass < 2; pass++) {
            int r  = (tid >> 3) + pass * 32;
            int dg = (tid & 7) * 4;
            size_t base = (size_t)(b * KLEN + k0 + r) * CC + h * DD + dg;
            float4 xk = *(const float4*)(g_kp + base);
            float4 xv = *(const float4*)(g_vp + base);
            kts[dg + 0][r] = xk.x; kts[dg + 1][r] = xk.y;
            kts[dg + 2][r] = xk.z; kts[dg + 3][r] = xk.w;
            *(float4*)&vs[r][dg] = xv;
        }
        __syncthreads();

        // Score micro-GEMM: s[4 rows][4 keys] over d=0..31.
        float acc[4][4] = {};
        #pragma unroll
        for (int d = 0; d < 32; d++) {
            float4 a4 = *(const float4*)&qs[d][ty * 4];
            float4 b4 = *(const float4*)&kts[d][tx * 4];
            float av[4] = {a4.x, a4.y, a4.z, a4.w};
            float bv[4] = {b4.x, b4.y, b4.z, b4.w};
            #pragma unroll
            for (int i = 0; i < 4; i++)
                #pragma unroll
                for (int j = 0; j < 4; j++)
                    acc[i][j] = fmaf(av[i], bv[j], acc[i][j]);
        }

        // Add biases (streamed from global; coalesced float4).
        float4 mbv = *(const float4*)(mask_bias + b * KLEN + k0 + tx * 4);
        const float* pb = pair_bias
            + ((size_t)((b * HH + h) * QL + q0 + ty * 4)) * KLEN + k0 + tx * 4;
        #pragma unroll
        for (int i = 0; i < 4; i++) {
            float4 pv = *(const float4*)(pb + (size_t)i * KLEN);
            acc[i][0] += pv.x + mbv.x;
            acc[i][1] += pv.y + mbv.y;
            acc[i][2] += pv.z + mbv.z;
            acc[i][3] += pv.w + mbv.w;
        }

        // Online softmax. Row r's 16 contributors are one half-warp (same ty).
        #pragma unroll
        for (int i = 0; i < 4; i++) {
            const int r = ty * 4 + i;
            float rm = fmaxf(fmaxf(acc[i][0], acc[i][1]), fmaxf(acc[i][2], acc[i][3]));
            rm = fmaxf(rm, __shfl_xor_sync(0xffffffffu, rm, 8));
            rm = fmaxf(rm, __shfl_xor_sync(0xffffffffu, rm, 4));
            rm = fmaxf(rm, __shfl_xor_sync(0xffffffffu, rm, 2));
            rm = fmaxf(rm, __shfl_xor_sync(0xffffffffu, rm, 1));
            float mold = m_sh[r];              // converged read before lane-0 write
            float mnew = fmaxf(mold, rm);
            float rs = 0.0f;
            #pragma unroll
            for (int j = 0; j < 4; j++) {
                float p = __expf(acc[i][j] - mnew);
                acc[i][j] = p;
                rs += p;
            }
            rs += __shfl_xor_sync(0xffffffffu, rs, 8);
            rs += __shfl_xor_sync(0xffffffffu, rs, 4);
            rs += __shfl_xor_sync(0xffffffffu, rs, 2);
            rs += __shfl_xor_sync(0xffffffffu, rs, 1);
            if (tx == 0) {
                float f = __expf(mold - mnew);   // 0 on first tile (mold = -inf)
                f_sh[r] = f;
                l_sh[r] = l_sh[r] * f + rs;
                m_sh[r] = mnew;
            }
            *(float4*)&ps[r][tx * 4] = make_float4(acc[i][0], acc[i][1], acc[i][2], acc[i][3]);
        }
        __syncthreads();

        // AV micro-GEMM with online rescale. Thread owns 4 rows x 2 dims.
        #pragma unroll
        for (int i = 0; i < 4; i++) {
            float f = f_sh[ty * 4 + i];
            o[i][0] *= f;
            o[i][1] *= f;
        }
        #pragma unroll 4
        for (int kk = 0; kk < 64; kk += 4) {
            float4 p4[4];
            #pragma unroll
            for (int i = 0; i < 4; i++)
                p4[i] = *(const float4*)&ps[ty * 4 + i][kk];
            float2 v2[4];
            #pragma unroll
            for (int u = 0; u < 4; u++)
                v2[u] = *(const float2*)&vs[kk + u][tx * 2];
            #pragma unroll
            for (int i = 0; i < 4; i++) {
                float pa[4] = {p4[i].x, p4[i].y, p4[i].z, p4[i].w};
                #pragma unroll
                for (int u = 0; u < 4; u++) {
                    o[i][0] = fmaf(pa[u], v2[u].x, o[i][0]);
                    o[i][1] = fmaf(pa[u], v2[u].y, o[i][1]);
                }
            }
        }
        __syncthreads();
    }

    // Epilogue: normalize, apply gate, write to g_o.
    #pragma unroll
    for (int i = 0; i < 4; i++) {
        const int r = ty * 4 + i;
        float invl = 1.0f / l_sh[r];
        size_t base = (size_t)(b * QL + q0 + r) * CC + h * DD + tx * 2;
        float g0 = g_gp[base];
        float g1 = g_gp[base + 1];
        g_o[base]     = o[i][0] * invl * g0;
        g_o[base + 1] = o[i][1] * invl * g1;
    }
}

// ---------------------------------------------------------------------------
// kernel_launch: 3 graph-capturable launches on the default stream.
// ---------------------------------------------------------------------------
extern "C" void kernel_launch(void* const* d_in, const int* in_sizes, int n_in,
                              void* d_out, int out_size)
{
    (void)in_sizes; (void)n_in; (void)out_size;
    const float* q_x       = (const float*)d_in[0];
    const float* kv_x      = (const float*)d_in[1];
    const float* mask_bias = (const float*)d_in[2];
    const float* pair_bias = (const float*)d_in[3];
    const float* wq        = (const float*)d_in[4];
    const float* wk        = (const float*)d_in[5];
    const float* wv        = (const float*)d_in[6];
    const float* wg        = (const float*)d_in[7];
    const float* bg        = (const float*)d_in[8];
    const float* wo        = (const float*)d_in[9];
    const float* bo        = (const float*)d_in[10];
    float* out = (float*)d_out;

    // 4 projection GEMMs in one launch (blockIdx.z = mode 0..3)
    gemm_kernel<<<dim3(CC / 64, MM / 64, 4), 256>>>(
        q_x, kv_x, wq, wk, wv, wg, bg, wo, bo, nullptr, 0);

    // Fused flash attention + gating
    attn_kernel<<<dim3(QL / 64, HH, BB), 256>>>(mask_bias, pair_bias);

    // Output projection (mode 4)
    gemm_kernel<<<dim3(CC / 64, MM / 64, 1), 256>>>(
        q_x, kv_x, wq, wk, wv, wg, bg, wo, bo, out, 4);
}

// round 2
// speedup vs baseline: 2.0829x; 2.0829x over previous
#include <cuda_runtime.h>
#include <math_constants.h>

#define BB 4
#define QL 1024
#define KLEN 1024
#define CC 256
#define HH 8
#define DD 32
#define MM (BB * QL)

// Scratch device globals (no allocation allowed)
__device__ float g_qp[MM * CC];  // q / sqrt(D)   [b*Q+q][h*D+d]
__device__ float g_kp[MM * CC];
__device__ float g_vp[MM * CC];
__device__ float g_gp[MM * CC];  // sigmoid gate
__device__ float g_o [MM * CC];  // gated attention output

__device__ __forceinline__ unsigned f2tf(float f) {
    unsigned r;
    asm("cvt.rna.tf32.f32 %0, %1;" : "=r"(r) : "f"(f));
    return r;
}

__device__ __forceinline__ void mma_tf32(float c[4],
                                         unsigned a0, unsigned a1, unsigned a2, unsigned a3,
                                         unsigned b0, unsigned b1) {
    asm volatile(
        "mma.sync.aligned.m16n8k8.row.col.f32.tf32.tf32.f32 "
        "{%0,%1,%2,%3}, {%4,%5,%6,%7}, {%8,%9}, {%0,%1,%2,%3};"
        : "+f"(c[0]), "+f"(c[1]), "+f"(c[2]), "+f"(c[3])
        : "r"(a0), "r"(a1), "r"(a2), "r"(a3), "r"(b0), "r"(b1));
}

// ---------------------------------------------------------------------------
// tf32 GEMM: Y[m][n] = sum_k X[m][k]*W[n][k], M=4096 N=256 K=256.
// BM=64, BN=256 (full N), BK=32. 256 threads = 8 warps (2 m-warps x 4 n-warps).
// modes: 0 q(scale) 1 k 2 v 3 gate(sigmoid+bg) 4 out(+bo)
// ---------------------------------------------------------------------------
__global__ __launch_bounds__(256)
void gemm_tf32(const float* __restrict__ qx, const float* __restrict__ kvx,
               const float* __restrict__ wq, const float* __restrict__ wk,
               const float* __restrict__ wv, const float* __restrict__ wg,
               const float* __restrict__ bg, const float* __restrict__ wo,
               const float* __restrict__ bo, float* __restrict__ outp,
               int mode_base)
{
    __shared__ __align__(16) unsigned Xs[64][36];
    __shared__ __align__(16) unsigned Ws[256][36];

    const int mode = mode_base + blockIdx.z;
    const float* X; const float* W; const float* bias = nullptr; float* Y;
    switch (mode) {
        case 0:  X = qx;  W = wq; Y = g_qp; break;
        case 1:  X = kvx; W = wk; Y = g_kp; break;
        case 2:  X = kvx; W = wv; Y = g_vp; break;
        case 3:  X = qx;  W = wg; Y = g_gp; bias = bg; break;
        default: X = g_o; W = wo; Y = outp; bias = bo; break;
    }

    const int tid  = threadIdx.x;
    const int lane = tid & 31;
    const int warp = tid >> 5;
    const int wm = warp & 1;        // 0..1 -> 32-row half
    const int wn = warp >> 1;       // 0..3 -> 64-col slice
    const int g = lane >> 2, tig = lane & 3;
    const int m0 = blockIdx.x * 64;

    float acc[2][8][4] = {};

    for (int kk = 0; kk < CC; kk += 32) {
        // X tile: 64x32
        #pragma unroll
        for (int p = 0; p < 2; p++) {
            int r = (tid >> 3) + p * 32;
            int c = (tid & 7) * 4;
            float4 v = *(const float4*)(X + (size_t)(m0 + r) * CC + kk + c);
            Xs[r][c + 0] = f2tf(v.x); Xs[r][c + 1] = f2tf(v.y);
            Xs[r][c + 2] = f2tf(v.z); Xs[r][c + 3] = f2tf(v.w);
        }
        // W tile: 256x32
        #pragma unroll
        for (int p = 0; p < 8; p++) {
            int r = (tid >> 3) + p * 32;
            int c = (tid & 7) * 4;
            float4 v = *(const float4*)(W + (size_t)r * CC + kk + c);
            Ws[r][c + 0] = f2tf(v.x); Ws[r][c + 1] = f2tf(v.y);
            Ws[r][c + 2] = f2tf(v.z); Ws[r][c + 3] = f2tf(v.w);
        }
        __syncthreads();

        #pragma unroll
        for (int ks = 0; ks < 4; ks++) {
            unsigned a[2][4];
            #pragma unroll
            for (int mt = 0; mt < 2; mt++) {
                int r = wm * 32 + mt * 16;
                a[mt][0] = Xs[r + g    ][ks * 8 + tig];
                a[mt][1] = Xs[r + g + 8][ks * 8 + tig];
                a[mt][2] = Xs[r + g    ][ks * 8 + tig + 4];
                a[mt][3] = Xs[r + g + 8][ks * 8 + tig + 4];
            }
            #pragma unroll
            for (int nt = 0; nt < 8; nt++) {
                int n = wn * 64 + nt * 8;
                unsigned b0 = Ws[n + g][ks * 8 + tig];
                unsigned b1 = Ws[n + g][ks * 8 + tig + 4];
                mma_tf32(acc[0][nt], a[0][0], a[0][1], a[0][2], a[0][3], b0, b1);
                mma_tf32(acc[1][nt], a[1][0], a[1][1], a[1][2], a[1][3], b0, b1);
            }
        }
        __syncthreads();
    }

    // Epilogue
    #pragma unroll
    for (int mt = 0; mt < 2; mt++) {
        int row0 = m0 + wm * 32 + mt * 16 + g;
        #pragma unroll
        for (int nt = 0; nt < 8; nt++) {
            int col = wn * 64 + nt * 8 + 2 * tig;
            float v[4] = {acc[mt][nt][0], acc[mt][nt][1], acc[mt][nt][2], acc[mt][nt][3]};
            if (mode == 0) {
                #pragma unroll
                for (int u = 0; u < 4; u++) v[u] *= 0.17677669529663689f;
            } else if (mode == 3) {
                float b0v = bias[col], b1v = bias[col + 1];
                v[0] = 1.0f / (1.0f + __expf(-(v[0] + b0v)));
                v[1] = 1.0f / (1.0f + __expf(-(v[1] + b1v)));
                v[2] = 1.0f / (1.0f + __expf(-(v[2] + b0v)));
                v[3] = 1.0f / (1.0f + __expf(-(v[3] + b1v)));
            } else if (mode == 4) {
                float b0v = bias[col], b1v = bias[col + 1];
                v[0] += b0v; v[1] += b1v; v[2] += b0v; v[3] += b1v;
            }
            *(float2*)(Y + (size_t)row0 * CC + col)       = make_float2(v[0], v[1]);
            *(float2*)(Y + (size_t)(row0 + 8) * CC + col) = make_float2(v[2], v[3]);
        }
    }
}

// ---------------------------------------------------------------------------
// Fused flash attention + gating with tf32 mma.
// Grid (Q/64, H, B), 128 threads (4 warps, 16 query rows each).
// ---------------------------------------------------------------------------
__global__ __launch_bounds__(128)
void attn_tf32(const float* __restrict__ mask_bias,
               const float* __restrict__ pair_bias)
{
    __shared__ __align__(16) unsigned qs[64][36];   // [q][d]
    __shared__ __align__(16) unsigned ks[64][36];   // [key][d]
    __shared__ __align__(16) unsigned vs[64][36];   // [key][d]
    __shared__ __align__(16) unsigned ps[64][68];   // probs tf32 [q][key]

    const int tid  = threadIdx.x;
    const int lane = tid & 31;
    const int warp = tid >> 5;
    const int g = lane >> 2, tig = lane & 3;
    const int q0 = blockIdx.x * 64;
    const int h  = blockIdx.y;
    const int b  = blockIdx.z;
    const int wr = warp * 16;      // warp's row offset in tile

    // Load Q tile (64x32)
    #pragma unroll
    for (int p = 0; p < 4; p++) {
        int r = (tid >> 3) + p * 16;
        int c = (tid & 7) * 4;
        float4 v = *(const float4*)(g_qp + (size_t)(b * QL + q0 + r) * CC + h * DD + c);
        qs[r][c + 0] = f2tf(v.x); qs[r][c + 1] = f2tf(v.y);
        qs[r][c + 2] = f2tf(v.z); qs[r][c + 3] = f2tf(v.w);
    }

    float m_r[2] = {-CUDART_INF_F, -CUDART_INF_F};
    float l_r[2] = {0.0f, 0.0f};
    float o[4][4] = {};   // 4 dim-tiles x 4 accum regs

    for (int kt = 0; kt < 16; kt++) {
        const int k0 = kt * 64;
        // Load K and V tiles
        #pragma unroll
        for (int p = 0; p < 4; p++) {
            int r = (tid >> 3) + p * 16;
            int c = (tid & 7) * 4;
            size_t base = (size_t)(b * KLEN + k0 + r) * CC + h * DD + c;
            float4 vk = *(const float4*)(g_kp + base);
            float4 vv = *(const float4*)(g_vp + base);
            ks[r][c + 0] = f2tf(vk.x); ks[r][c + 1] = f2tf(vk.y);
            ks[r][c + 2] = f2tf(vk.z); ks[r][c + 3] = f2tf(vk.w);
            vs[r][c + 0] = f2tf(vv.x); vs[r][c + 1] = f2tf(vv.y);
            vs[r][c + 2] = f2tf(vv.z); vs[r][c + 3] = f2tf(vv.w);
        }
        __syncthreads();

        // Scores: S[16 x 64] per warp = 8 n-tiles
        float s[8][4] = {};
        #pragma unroll
        for (int kst = 0; kst < 4; kst++) {
            unsigned a0 = qs[wr + g    ][kst * 8 + tig];
            unsigned a1 = qs[wr + g + 8][kst * 8 + tig];
            unsigned a2 = qs[wr + g    ][kst * 8 + tig + 4];
            unsigned a3 = qs[wr + g + 8][kst * 8 + tig + 4];
            #pragma unroll
            for (int nt = 0; nt < 8; nt++) {
                unsigned b0 = ks[nt * 8 + g][kst * 8 + tig];
                unsigned b1 = ks[nt * 8 + g][kst * 8 + tig + 4];
                mma_tf32(s[nt], a0, a1, a2, a3, b0, b1);
            }
        }

        // Add biases
        const float* pb0 = pair_bias
            + ((size_t)((b * HH + h) * QL + q0 + wr + g)) * KLEN + k0;
        #pragma unroll
        for (int nt = 0; nt < 8; nt++) {
            int col = nt * 8 + 2 * tig;
            float2 mb = *(const float2*)(mask_bias + (size_t)b * KLEN + k0 + col);
            float2 p0 = *(const float2*)(pb0 + col);
            float2 p1 = *(const float2*)(pb0 + 8 * (size_t)KLEN + col);
            s[nt][0] += p0.x + mb.x;
            s[nt][1] += p0.y + mb.y;
            s[nt][2] += p1.x + mb.x;
            s[nt][3] += p1.y + mb.y;
        }

        // Row max (rows g and g+8), quad reduction
        float rm0 = -CUDART_INF_F, rm1 = -CUDART_INF_F;
        #pragma unroll
        for (int nt = 0; nt < 8; nt++) {
            rm0 = fmaxf(rm0, fmaxf(s[nt][0], s[nt][1]));
            rm1 = fmaxf(rm1, fmaxf(s[nt][2], s[nt][3]));
        }
        rm0 = fmaxf(rm0, __shfl_xor_sync(0xffffffffu, rm0, 1));
        rm0 = fmaxf(rm0, __shfl_xor_sync(0xffffffffu, rm0, 2));
        rm1 = fmaxf(rm1, __shfl_xor_sync(0xffffffffu, rm1, 1));
        rm1 = fmaxf(rm1, __shfl_xor_sync(0xffffffffu, rm1, 2));
        float mn0 = fmaxf(m_r[0], rm0);
        float mn1 = fmaxf(m_r[1], rm1);

        float rs0 = 0.0f, rs1 = 0.0f;
        #pragma unroll
        for (int nt = 0; nt < 8; nt++) {
            s[nt][0] = __expf(s[nt][0] - mn0);
            s[nt][1] = __expf(s[nt][1] - mn0);
            s[nt][2] = __expf(s[nt][2] - mn1);
            s[nt][3] = __expf(s[nt][3] - mn1);
            rs0 += s[nt][0] + s[nt][1];
            rs1 += s[nt][2] + s[nt][3];
        }
        rs0 += __shfl_xor_sync(0xffffffffu, rs0, 1);
        rs0 += __shfl_xor_sync(0xffffffffu, rs0, 2);
        rs1 += __shfl_xor_sync(0xffffffffu, rs1, 1);
        rs1 += __shfl_xor_sync(0xffffffffu, rs1, 2);

        float f0 = __expf(m_r[0] - mn0);   // 0 on first tile
        float f1 = __expf(m_r[1] - mn1);
        l_r[0] = l_r[0] * f0 + rs0;  m_r[0] = mn0;
        l_r[1] = l_r[1] * f1 + rs1;  m_r[1] = mn1;

        #pragma unroll
        for (int nt = 0; nt < 4; nt++) {
            o[nt][0] *= f0; o[nt][1] *= f0;
            o[nt][2] *= f1; o[nt][3] *= f1;
        }

        // Write P to smem as tf32 (per-warp private rows)
        #pragma unroll
        for (int nt = 0; nt < 8; nt++) {
            int col = nt * 8 + 2 * tig;
            ps[wr + g    ][col]     = f2tf(s[nt][0]);
            ps[wr + g    ][col + 1] = f2tf(s[nt][1]);
            ps[wr + g + 8][col]     = f2tf(s[nt][2]);
            ps[wr + g + 8][col + 1] = f2tf(s[nt][3]);
        }
        __syncwarp();

        // O += P @ V : 8 k-steps over 64 keys, 4 dim-tiles
        #pragma unroll
        for (int kst = 0; kst < 8; kst++) {
            unsigned a0 = ps[wr + g    ][kst * 8 + tig];
            unsigned a1 = ps[wr + g + 8][kst * 8 + tig];
            unsigned a2 = ps[wr + g    ][kst * 8 + tig + 4];
            unsigned a3 = ps[wr + g + 8][kst * 8 + tig + 4];
            #pragma unroll
            for (int nt = 0; nt < 4; nt++) {
                unsigned b0 = vs[kst * 8 + tig    ][nt * 8 + g];
                unsigned b1 = vs[kst * 8 + tig + 4][nt * 8 + g];
                mma_tf32(o[nt], a0, a1, a2, a3, b0, b1);
            }
        }
        __syncthreads();
    }

    // Epilogue: normalize, gate, write g_o
    float invl0 = 1.0f / l_r[0];
    float invl1 = 1.0f / l_r[1];
    #pragma unroll
    for (int nt = 0; nt < 4; nt++) {
        int col = nt * 8 + 2 * tig;
        size_t base0 = (size_t)(b * QL + q0 + wr + g) * CC + h * DD + col;
        size_t base1 = base0 + 8 * (size_t)CC;
        float2 ga = *(const float2*)(g_gp + base0);
        float2 gb = *(const float2*)(g_gp + base1);
        *(float2*)(g_o + base0) = make_float2(o[nt][0] * invl0 * ga.x,
                                              o[nt][1] * invl0 * ga.y);
        *(float2*)(g_o + base1) = make_float2(o[nt][2] * invl1 * gb.x,
                                              o[nt][3] * invl1 * gb.y);
    }
}

// ---------------------------------------------------------------------------
extern "C" void kernel_launch(void* const* d_in, const int* in_sizes, int n_in,
                              void* d_out, int out_size)
{
    (void)in_sizes; (void)n_in; (void)out_size;
    const float* q_x       = (const float*)d_in[0];
    const float* kv_x      = (const float*)d_in[1];
    const float* mask_bias = (const float*)d_in[2];
    const float* pair_bias = (const float*)d_in[3];
    const float* wq        = (const float*)d_in[4];
    const float* wk        = (const float*)d_in[5];
    const float* wv        = (const float*)d_in[6];
    const float* wg        = (const float*)d_in[7];
    const float* bg        = (const float*)d_in[8];
    const float* wo        = (const float*)d_in[9];
    const float* bo        = (const float*)d_in[10];
    float* out = (float*)d_out;

    gemm_tf32<<<dim3(MM / 64, 1, 4), 256>>>(
        q_x, kv_x, wq, wk, wv, wg, bg, wo, bo, nullptr, 0);

    attn_tf32<<<dim3(QL / 64, HH, BB), 128>>>(mask_bias, pair_bias);

    gemm_tf32<<<dim3(MM / 64, 1, 1), 256>>>(
        q_x, kv_x, wq, wk, wv, wg, bg, wo, bo, out, 4);
}

// round 3
// speedup vs baseline: 2.4681x; 1.1849x over previous
#include <cuda_runtime.h>
#include <math_constants.h>

#define BB 4
#define QL 1024
#define KLEN 1024
#define CC 256
#define HH 8
#define DD 32
#define MM (BB * QL)

// Scratch device globals (no allocation allowed)
__device__ float g_qp[MM * CC];  // q/sqrt(D), stored as tf32 bit-patterns
__device__ float g_kp[MM * CC];  // tf32 bit-patterns
__device__ float g_vp[MM * CC];  // tf32 bit-patterns
__device__ float g_gp[MM * CC];  // sigmoid gate, fp32
__device__ float g_o [MM * CC];  // gated attention output, fp32

__device__ __forceinline__ unsigned f2tf(float f) {
    unsigned r;
    asm("cvt.rna.tf32.f32 %0, %1;" : "=r"(r) : "f"(f));
    return r;
}

__device__ __forceinline__ void mma_tf32(float c[4],
                                         unsigned a0, unsigned a1, unsigned a2, unsigned a3,
                                         unsigned b0, unsigned b1) {
    asm volatile(
        "mma.sync.aligned.m16n8k8.row.col.f32.tf32.tf32.f32 "
        "{%0,%1,%2,%3}, {%4,%5,%6,%7}, {%8,%9}, {%0,%1,%2,%3};"
        : "+f"(c[0]), "+f"(c[1]), "+f"(c[2]), "+f"(c[3])
        : "r"(a0), "r"(a1), "r"(a2), "r"(a3), "r"(b0), "r"(b1));
}

__device__ __forceinline__ void cp16(void* dst_smem, const void* src) {
    unsigned d = (unsigned)__cvta_generic_to_shared(dst_smem);
    asm volatile("cp.async.cg.shared.global [%0], [%1], 16;" :: "r"(d), "l"(src));
}
#define CP_COMMIT() asm volatile("cp.async.commit_group;")
#define CP_WAIT0()  asm volatile("cp.async.wait_group 0;")

// ---------------------------------------------------------------------------
// tf32 GEMM: Y[m][n] = sum_k X[m][k]*W[n][k]; M=4096 N=256 K=256.
// BM=64 BN=128 BK=32, 256 thr (2 m-warps x 4 n-warps), register-prefetch pipe.
// modes: 0 q(scale,tf32-out) 1 k(tf32) 2 v(tf32) 3 gate(sigmoid) 4 out(+bo)
// ---------------------------------------------------------------------------
__global__ __launch_bounds__(256)
void gemm_tf32(const float* __restrict__ qx, const float* __restrict__ kvx,
               const float* __restrict__ wq, const float* __restrict__ wk,
               const float* __restrict__ wv, const float* __restrict__ wg,
               const float* __restrict__ bg, const float* __restrict__ wo,
               const float* __restrict__ bo, float* __restrict__ outp,
               int mode_base)
{
    __shared__ __align__(16) unsigned Xs[64][36];
    __shared__ __align__(16) unsigned Ws[128][36];

    const int mode = mode_base + blockIdx.z;
    const float* X; const float* W; const float* bias = nullptr; float* Y;
    switch (mode) {
        case 0:  X = qx;  W = wq; Y = g_qp; break;
        case 1:  X = kvx; W = wk; Y = g_kp; break;
        case 2:  X = kvx; W = wv; Y = g_vp; break;
        case 3:  X = qx;  W = wg; Y = g_gp; bias = bg; break;
        default: X = g_o; W = wo; Y = outp; bias = bo; break;
    }

    const int tid  = threadIdx.x;
    const int lane = tid & 31;
    const int warp = tid >> 5;
    const int wm = warp & 1;
    const int wn = warp >> 1;
    const int g = lane >> 2, tig = lane & 3;
    const int m0 = blockIdx.x * 64;
    const int n0 = blockIdx.y * 128;

    const int lr = tid >> 3;          // 0..31
    const int lc = (tid & 7) * 4;     // 0..28

    float acc[2][4][4] = {};
    float4 xr[2], wr4[4];

    // preload tile kk=0 into registers
    #pragma unroll
    for (int p = 0; p < 2; p++)
        xr[p] = *(const float4*)(X + (size_t)(m0 + lr + p * 32) * CC + lc);
    #pragma unroll
    for (int p = 0; p < 4; p++)
        wr4[p] = *(const float4*)(W + (size_t)(n0 + lr + p * 32) * CC + lc);

    for (int kk = 0; kk < CC; kk += 32) {
        // store current regs (convert to tf32)
        #pragma unroll
        for (int p = 0; p < 2; p++) {
            int r = lr + p * 32;
            Xs[r][lc + 0] = f2tf(xr[p].x); Xs[r][lc + 1] = f2tf(xr[p].y);
            Xs[r][lc + 2] = f2tf(xr[p].z); Xs[r][lc + 3] = f2tf(xr[p].w);
        }
        #pragma unroll
        for (int p = 0; p < 4; p++) {
            int r = lr + p * 32;
            Ws[r][lc + 0] = f2tf(wr4[p].x); Ws[r][lc + 1] = f2tf(wr4[p].y);
            Ws[r][lc + 2] = f2tf(wr4[p].z); Ws[r][lc + 3] = f2tf(wr4[p].w);
        }
        __syncthreads();

        // prefetch next tile (overlaps the mma below)
        if (kk + 32 < CC) {
            #pragma unroll
            for (int p = 0; p < 2; p++)
                xr[p] = *(const float4*)(X + (size_t)(m0 + lr + p * 32) * CC + kk + 32 + lc);
            #pragma unroll
            for (int p = 0; p < 4; p++)
                wr4[p] = *(const float4*)(W + (size_t)(n0 + lr + p * 32) * CC + kk + 32 + lc);
        }

        #pragma unroll
        for (int ks = 0; ks < 4; ks++) {
            unsigned a[2][4];
            #pragma unroll
            for (int mt = 0; mt < 2; mt++) {
                int r = wm * 32 + mt * 16;
                a[mt][0] = Xs[r + g    ][ks * 8 + tig];
                a[mt][1] = Xs[r + g + 8][ks * 8 + tig];
                a[mt][2] = Xs[r + g    ][ks * 8 + tig + 4];
                a[mt][3] = Xs[r + g + 8][ks * 8 + tig + 4];
            }
            #pragma unroll
            for (int nt = 0; nt < 4; nt++) {
                int n = wn * 32 + nt * 8;
                unsigned b0 = Ws[n + g][ks * 8 + tig];
                unsigned b1 = Ws[n + g][ks * 8 + tig + 4];
                mma_tf32(acc[0][nt], a[0][0], a[0][1], a[0][2], a[0][3], b0, b1);
                mma_tf32(acc[1][nt], a[1][0], a[1][1], a[1][2], a[1][3], b0, b1);
            }
        }
        __syncthreads();
    }

    #pragma unroll
    for (int mt = 0; mt < 2; mt++) {
        int row0 = m0 + wm * 32 + mt * 16 + g;
        #pragma unroll
        for (int nt = 0; nt < 4; nt++) {
            int col = n0 + wn * 32 + nt * 8 + 2 * tig;
            float v[4] = {acc[mt][nt][0], acc[mt][nt][1], acc[mt][nt][2], acc[mt][nt][3]};
            if (mode == 0) {
                #pragma unroll
                for (int u = 0; u < 4; u++) v[u] *= 0.17677669529663689f;
            } else if (mode == 3) {
                float b0v = bias[col], b1v = bias[col + 1];
                v[0] = 1.0f / (1.0f + __expf(-(v[0] + b0v)));
                v[1] = 1.0f / (1.0f + __expf(-(v[1] + b1v)));
                v[2] = 1.0f / (1.0f + __expf(-(v[2] + b0v)));
                v[3] = 1.0f / (1.0f + __expf(-(v[3] + b1v)));
            } else if (mode == 4) {
                float b0v = bias[col], b1v = bias[col + 1];
                v[0] += b0v; v[1] += b1v; v[2] += b0v; v[3] += b1v;
            }
            if (mode <= 2) {   // pre-convert q/k/v to tf32 bit-patterns
                #pragma unroll
                for (int u = 0; u < 4; u++) v[u] = __uint_as_float(f2tf(v[u]));
            }
            *(float2*)(Y + (size_t)row0 * CC + col)       = make_float2(v[0], v[1]);
            *(float2*)(Y + (size_t)(row0 + 8) * CC + col) = make_float2(v[2], v[3]);
        }
    }
}

// ---------------------------------------------------------------------------
// Fused flash attention + gating. cp.async double-buffered K/V, hoisted bias
// loads, shuffle-based P->A fragment remap (no smem round-trip).
// Grid (Q/64, H, B), 128 threads (4 warps x 16 query rows).
// ---------------------------------------------------------------------------
__global__ __launch_bounds__(128)
void attn_tf32(const float* __restrict__ mask_bias,
               const float* __restrict__ pair_bias)
{
    __shared__ __align__(16) unsigned qs[64][36];      // [q][d] tf32
    __shared__ __align__(16) unsigned ks[2][64][36];   // double-buffered
    __shared__ __align__(16) unsigned vs[2][64][36];

    const int tid  = threadIdx.x;
    const int lane = tid & 31;
    const int warp = tid >> 5;
    const int g = lane >> 2, tig = lane & 3;
    const int q0 = blockIdx.x * 64;
    const int h  = blockIdx.y;
    const int b  = blockIdx.z;
    const int wr = warp * 16;

    const int lr = tid >> 3;          // 0..15
    const int lc = (tid & 7) * 4;     // 0..28

    // async load Q tile + K/V tile 0
    #pragma unroll
    for (int p = 0; p < 4; p++) {
        int r = lr + p * 16;
        cp16(&qs[r][lc], g_qp + (size_t)(b * QL + q0 + r) * CC + h * DD + lc);
    }
    #pragma unroll
    for (int p = 0; p < 4; p++) {
        int r = lr + p * 16;
        size_t base = (size_t)(b * KLEN + r) * CC + h * DD + lc;
        cp16(&ks[0][r][lc], g_kp + base);
        cp16(&vs[0][r][lc], g_vp + base);
    }
    CP_COMMIT();
    CP_WAIT0();
    __syncthreads();

    float m_r[2] = {-CUDART_INF_F, -CUDART_INF_F};
    float l_r[2] = {0.0f, 0.0f};
    float o[4][4] = {};

    for (int kt = 0; kt < 16; kt++) {
        const int k0 = kt * 64;
        const int cur = kt & 1;

        // prefetch next K/V tile into the other buffer
        if (kt < 15) {
            #pragma unroll
            for (int p = 0; p < 4; p++) {
                int r = lr + p * 16;
                size_t base = (size_t)(b * KLEN + k0 + 64 + r) * CC + h * DD + lc;
                cp16(&ks[cur ^ 1][r][lc], g_kp + base);
                cp16(&vs[cur ^ 1][r][lc], g_vp + base);
            }
            CP_COMMIT();
        }

        // hoisted bias loads (consumed after the QK mma)
        float2 mb[8], p0[8], p1[8];
        const float* pb0 = pair_bias
            + ((size_t)((b * HH + h) * QL + q0 + wr + g)) * KLEN + k0;
        #pragma unroll
        for (int nt = 0; nt < 8; nt++) {
            int col = nt * 8 + 2 * tig;
            mb[nt] = *(const float2*)(mask_bias + (size_t)b * KLEN + k0 + col);
            p0[nt] = *(const float2*)(pb0 + col);
            p1[nt] = *(const float2*)(pb0 + 8 * (size_t)KLEN + col);
        }

        // QK^T scores
        float s[8][4] = {};
        #pragma unroll
        for (int kst = 0; kst < 4; kst++) {
            unsigned a0 = qs[wr + g    ][kst * 8 + tig];
            unsigned a1 = qs[wr + g + 8][kst * 8 + tig];
            unsigned a2 = qs[wr + g    ][kst * 8 + tig + 4];
            unsigned a3 = qs[wr + g + 8][kst * 8 + tig + 4];
            #pragma unroll
            for (int nt = 0; nt < 8; nt++) {
                unsigned b0 = ks[cur][nt * 8 + g][kst * 8 + tig];
                unsigned b1 = ks[cur][nt * 8 + g][kst * 8 + tig + 4];
                mma_tf32(s[nt], a0, a1, a2, a3, b0, b1);
            }
        }

        #pragma unroll
        for (int nt = 0; nt < 8; nt++) {
            s[nt][0] += p0[nt].x + mb[nt].x;
            s[nt][1] += p0[nt].y + mb[nt].y;
            s[nt][2] += p1[nt].x + mb[nt].x;
            s[nt][3] += p1[nt].y + mb[nt].y;
        }

        // online softmax (rows g, g+8)
        float rm0 = -CUDART_INF_F, rm1 = -CUDART_INF_F;
        #pragma unroll
        for (int nt = 0; nt < 8; nt++) {
            rm0 = fmaxf(rm0, fmaxf(s[nt][0], s[nt][1]));
            rm1 = fmaxf(rm1, fmaxf(s[nt][2], s[nt][3]));
        }
        rm0 = fmaxf(rm0, __shfl_xor_sync(0xffffffffu, rm0, 1));
        rm0 = fmaxf(rm0, __shfl_xor_sync(0xffffffffu, rm0, 2));
        rm1 = fmaxf(rm1, __shfl_xor_sync(0xffffffffu, rm1, 1));
        rm1 = fmaxf(rm1, __shfl_xor_sync(0xffffffffu, rm1, 2));
        float mn0 = fmaxf(m_r[0], rm0);
        float mn1 = fmaxf(m_r[1], rm1);

        float rs0 = 0.0f, rs1 = 0.0f;
        #pragma unroll
        for (int nt = 0; nt < 8; nt++) {
            s[nt][0] = __expf(s[nt][0] - mn0);
            s[nt][1] = __expf(s[nt][1] - mn0);
            s[nt][2] = __expf(s[nt][2] - mn1);
            s[nt][3] = __expf(s[nt][3] - mn1);
            rs0 += s[nt][0] + s[nt][1];
            rs1 += s[nt][2] + s[nt][3];
        }
        rs0 += __shfl_xor_sync(0xffffffffu, rs0, 1);
        rs0 += __shfl_xor_sync(0xffffffffu, rs0, 2);
        rs1 += __shfl_xor_sync(0xffffffffu, rs1, 1);
        rs1 += __shfl_xor_sync(0xffffffffu, rs1, 2);

        float f0 = __expf(m_r[0] - mn0);
        float f1 = __expf(m_r[1] - mn1);
        l_r[0] = l_r[0] * f0 + rs0;  m_r[0] = mn0;
        l_r[1] = l_r[1] * f1 + rs1;  m_r[1] = mn1;

        #pragma unroll
        for (int nt = 0; nt < 4; nt++) {
            o[nt][0] *= f0; o[nt][1] *= f0;
            o[nt][2] *= f1; o[nt][3] *= f1;
        }

        // AV: remap P (C-layout) -> A-fragments via quad shuffles
        #pragma unroll
        for (int kst = 0; kst < 8; kst++) {
            int src0 = (lane & ~3) | (tig >> 1);
            int src1 = src0 + 2;
            float e0 = __shfl_sync(0xffffffffu, s[kst][0], src0);
            float e1 = __shfl_sync(0xffffffffu, s[kst][1], src0);
            float e2 = __shfl_sync(0xffffffffu, s[kst][2], src0);
            float e3 = __shfl_sync(0xffffffffu, s[kst][3], src0);
            float h0 = __shfl_sync(0xffffffffu, s[kst][0], src1);
            float h1 = __shfl_sync(0xffffffffu, s[kst][1], src1);
            float h2 = __shfl_sync(0xffffffffu, s[kst][2], src1);
            float h3 = __shfl_sync(0xffffffffu, s[kst][3], src1);
            bool odd = (tig & 1);
            unsigned a0 = f2tf(odd ? e1 : e0);   // row g,   col kst*8+tig
            unsigned a1 = f2tf(odd ? e3 : e2);   // row g+8, col kst*8+tig
            unsigned a2 = f2tf(odd ? h1 : h0);   // row g,   col kst*8+tig+4
            unsigned a3 = f2tf(odd ? h3 : h2);   // row g+8, col kst*8+tig+4
            #pragma unroll
            for (int nt = 0; nt < 4; nt++) {
                unsigned b0 = vs[cur][kst * 8 + tig    ][nt * 8 + g];
                unsigned b1 = vs[cur][kst * 8 + tig + 4][nt * 8 + g];
                mma_tf32(o[nt], a0, a1, a2, a3, b0, b1);
            }
        }

        CP_WAIT0();
        __syncthreads();
    }

    // Epilogue: normalize, gate, write g_o
    float invl0 = 1.0f / l_r[0];
    float invl1 = 1.0f / l_r[1];
    #pragma unroll
    for (int nt = 0; nt < 4; nt++) {
        int col = nt * 8 + 2 * tig;
        size_t base0 = (size_t)(b * QL + q0 + wr + g) * CC + h * DD + col;
        size_t base1 = base0 + 8 * (size_t)CC;
        float2 ga = *(const float2*)(g_gp + base0);
        float2 gb = *(const float2*)(g_gp + base1);
        *(float2*)(g_o + base0) = make_float2(o[nt][0] * invl0 * ga.x,
                                              o[nt][1] * invl0 * ga.y);
        *(float2*)(g_o + base1) = make_float2(o[nt][2] * invl1 * gb.x,
                                              o[nt][3] * invl1 * gb.y);
    }
}

// ---------------------------------------------------------------------------
extern "C" void kernel_launch(void* const* d_in, const int* in_sizes, int n_in,
                              void* d_out, int out_size)
{
    (void)in_sizes; (void)n_in; (void)out_size;
    const float* q_x       = (const float*)d_in[0];
    const float* kv_x      = (const float*)d_in[1];
    const float* mask_bias = (const float*)d_in[2];
    const float* pair_bias = (const float*)d_in[3];
    const float* wq        = (const float*)d_in[4];
    const float* wk        = (const float*)d_in[5];
    const float* wv        = (const float*)d_in[6];
    const float* wg        = (const float*)d_in[7];
    const float* bg        = (const float*)d_in[8];
    const float* wo        = (const float*)d_in[9];
    const float* bo        = (const float*)d_in[10];
    float* out = (float*)d_out;

    gemm_tf32<<<dim3(MM / 64, CC / 128, 4), 256>>>(
        q_x, kv_x, wq, wk, wv, wg, bg, wo, bo, nullptr, 0);

    attn_tf32<<<dim3(QL / 64, HH, BB), 128>>>(mask_bias, pair_bias);

    gemm_tf32<<<dim3(MM / 64, CC / 128, 1), 256>>>(
        q_x, kv_x, wq, wk, wv, wg, bg, wo, bo, out, 4);
}

// round 4
// speedup vs baseline: 2.5425x; 1.0302x over previous
#include <cuda_runtime.h>
#include <math_constants.h>

#define BB 4
#define QL 1024
#define KLEN 1024
#define CC 256
#define HH 8
#define DD 32
#define MM (BB * QL)

// Scratch device globals (no allocation allowed). All tf32 values stored as
// float-typed bit patterns.
__device__ float g_xq [MM * CC];   // tf32(q_x)
__device__ float g_xkv[MM * CC];   // tf32(kv_x)
__device__ float g_wts[5 * CC * CC]; // tf32(wq,wk,wv,wg,wo) concatenated
__device__ float g_qp[MM * CC];    // tf32(q/sqrt(D))
__device__ float g_kp[MM * CC];    // tf32(k)
__device__ float g_vp[MM * CC];    // tf32(v)
__device__ float g_gp[MM * CC];    // sigmoid gate (fp32)
__device__ float g_o [MM * CC];    // tf32(gated attention output)

__device__ __forceinline__ unsigned f2tf(float f) {
    unsigned r;
    asm("cvt.rna.tf32.f32 %0, %1;" : "=r"(r) : "f"(f));
    return r;
}

__device__ __forceinline__ void mma_tf32(float c[4],
                                         unsigned a0, unsigned a1, unsigned a2, unsigned a3,
                                         unsigned b0, unsigned b1) {
    asm volatile(
        "mma.sync.aligned.m16n8k8.row.col.f32.tf32.tf32.f32 "
        "{%0,%1,%2,%3}, {%4,%5,%6,%7}, {%8,%9}, {%0,%1,%2,%3};"
        : "+f"(c[0]), "+f"(c[1]), "+f"(c[2]), "+f"(c[3])
        : "r"(a0), "r"(a1), "r"(a2), "r"(a3), "r"(b0), "r"(b1));
}

__device__ __forceinline__ void cp16(void* dst_smem, const void* src) {
    unsigned d = (unsigned)__cvta_generic_to_shared(dst_smem);
    asm volatile("cp.async.cg.shared.global [%0], [%1], 16;" :: "r"(d), "l"(src));
}
#define CP_COMMIT() asm volatile("cp.async.commit_group;")
#define CP_WAIT0()  asm volatile("cp.async.wait_group 0;")
#define CP_WAIT1()  asm volatile("cp.async.wait_group 1;")

// ---------------------------------------------------------------------------
// Prep: RNA-convert q_x, kv_x, and the five weight matrices to tf32 once.
// Grid (1024, 3) x 256 threads; one float4 per thread.
// ---------------------------------------------------------------------------
__global__ __launch_bounds__(256)
void prep_tf32(const float* __restrict__ qx, const float* __restrict__ kvx,
               const float* __restrict__ wq, const float* __restrict__ wk,
               const float* __restrict__ wv, const float* __restrict__ wg,
               const float* __restrict__ wo)
{
    const int seg = blockIdx.y;
    const int i4 = blockIdx.x * 256 + threadIdx.x;
    const float* src; float* dst; int idx = i4;
    if (seg == 0)      { src = qx;  dst = g_xq;  }
    else if (seg == 1) { src = kvx; dst = g_xkv; }
    else {
        if (i4 >= 5 * CC * CC / 4) return;
        int w = i4 / (CC * CC / 4);
        idx = i4 - w * (CC * CC / 4);
        const float* ws[5] = {wq, wk, wv, wg, wo};
        src = ws[w];
        dst = g_wts + (size_t)w * CC * CC;
    }
    float4 v = ((const float4*)src)[idx];
    float4 o;
    o.x = __uint_as_float(f2tf(v.x)); o.y = __uint_as_float(f2tf(v.y));
    o.z = __uint_as_float(f2tf(v.z)); o.w = __uint_as_float(f2tf(v.w));
    ((float4*)dst)[idx] = o;
}

// ---------------------------------------------------------------------------
// tf32 GEMM v2: all operands pre-converted; 2-stage cp.async pipeline.
// Y[m][n] = sum_k X[m][k]*W[n][k]; BM=64 BN=128 BK=32; 256 threads.
// Dynamic smem: Xs[2][64][36] + Ws[2][128][36] = 55296 B.
// ---------------------------------------------------------------------------
#define GEMM_SMEM (2 * 64 * 36 * 4 + 2 * 128 * 36 * 4)

__global__ __launch_bounds__(256)
void gemm_tf32(const float* __restrict__ bg, const float* __restrict__ bo,
               float* __restrict__ outp, int mode_base)
{
    extern __shared__ float sm[];
    float* Xs = sm;                 // [2][64][36]
    float* Ws = sm + 2 * 64 * 36;   // [2][128][36]

    const int mode = mode_base + blockIdx.z;
    const float* X; const float* W; const float* bias = nullptr; float* Y;
    switch (mode) {
        case 0:  X = g_xq;  W = g_wts;              Y = g_qp; break;
        case 1:  X = g_xkv; W = g_wts + 1 * CC * CC; Y = g_kp; break;
        case 2:  X = g_xkv; W = g_wts + 2 * CC * CC; Y = g_vp; break;
        case 3:  X = g_xq;  W = g_wts + 3 * CC * CC; Y = g_gp; bias = bg; break;
        default: X = g_o;   W = g_wts + 4 * CC * CC; Y = outp; bias = bo; break;
    }

    const int tid  = threadIdx.x;
    const int lane = tid & 31;
    const int warp = tid >> 5;
    const int wm = warp & 1;
    const int wn = warp >> 1;
    const int g = lane >> 2, tig = lane & 3;
    const int m0 = blockIdx.x * 64;
    const int n0 = blockIdx.y * 128;

    auto loadTiles = [&](int st, int kk) {
        // X: 64 rows x 8 chunks = 512 chunks, 2/thread
        #pragma unroll
        for (int p = 0; p < 2; p++) {
            int ch = tid + p * 256;
            int r = ch >> 3, c = (ch & 7) * 4;
            cp16(Xs + (st * 64 + r) * 36 + c, X + (size_t)(m0 + r) * CC + kk + c);
        }
        // W: 128 rows x 8 chunks = 1024 chunks, 4/thread
        #pragma unroll
        for (int p = 0; p < 4; p++) {
            int ch = tid + p * 256;
            int r = ch >> 3, c = (ch & 7) * 4;
            cp16(Ws + (st * 128 + r) * 36 + c, W + (size_t)(n0 + r) * CC + kk + c);
        }
    };

    float acc[2][4][4] = {};

    loadTiles(0, 0);
    CP_COMMIT();

    for (int kt = 0; kt < CC / 32; kt++) {
        const int st = kt & 1;
        if (kt + 1 < CC / 32) {
            loadTiles(st ^ 1, (kt + 1) * 32);
            CP_COMMIT();
            CP_WAIT1();
        } else {
            CP_WAIT0();
        }
        __syncthreads();

        const float* Xb = Xs + st * 64 * 36;
        const float* Wb = Ws + st * 128 * 36;
        #pragma unroll
        for (int ks = 0; ks < 4; ks++) {
            unsigned a[2][4];
            #pragma unroll
            for (int mt = 0; mt < 2; mt++) {
                int r = wm * 32 + mt * 16;
                a[mt][0] = __float_as_uint(Xb[(r + g    ) * 36 + ks * 8 + tig]);
                a[mt][1] = __float_as_uint(Xb[(r + g + 8) * 36 + ks * 8 + tig]);
                a[mt][2] = __float_as_uint(Xb[(r + g    ) * 36 + ks * 8 + tig + 4]);
                a[mt][3] = __float_as_uint(Xb[(r + g + 8) * 36 + ks * 8 + tig + 4]);
            }
            #pragma unroll
            for (int nt = 0; nt < 4; nt++) {
                int n = wn * 32 + nt * 8;
                unsigned b0 = __float_as_uint(Wb[(n + g) * 36 + ks * 8 + tig]);
                unsigned b1 = __float_as_uint(Wb[(n + g) * 36 + ks * 8 + tig + 4]);
                mma_tf32(acc[0][nt], a[0][0], a[0][1], a[0][2], a[0][3], b0, b1);
                mma_tf32(acc[1][nt], a[1][0], a[1][1], a[1][2], a[1][3], b0, b1);
            }
        }
        __syncthreads();
    }

    #pragma unroll
    for (int mt = 0; mt < 2; mt++) {
        int row0 = m0 + wm * 32 + mt * 16 + g;
        #pragma unroll
        for (int nt = 0; nt < 4; nt++) {
            int col = n0 + wn * 32 + nt * 8 + 2 * tig;
            float v[4] = {acc[mt][nt][0], acc[mt][nt][1], acc[mt][nt][2], acc[mt][nt][3]};
            if (mode == 0) {
                #pragma unroll
                for (int u = 0; u < 4; u++) v[u] *= 0.17677669529663689f;
            } else if (mode == 3) {
                float b0v = bias[col], b1v = bias[col + 1];
                v[0] = 1.0f / (1.0f + __expf(-(v[0] + b0v)));
                v[1] = 1.0f / (1.0f + __expf(-(v[1] + b1v)));
                v[2] = 1.0f / (1.0f + __expf(-(v[2] + b0v)));
                v[3] = 1.0f / (1.0f + __expf(-(v[3] + b1v)));
            } else if (mode == 4) {
                float b0v = bias[col], b1v = bias[col + 1];
                v[0] += b0v; v[1] += b1v; v[2] += b0v; v[3] += b1v;
            }
            if (mode <= 2) {
                #pragma unroll
                for (int u = 0; u < 4; u++) v[u] = __uint_as_float(f2tf(v[u]));
            }
            *(float2*)(Y + (size_t)row0 * CC + col)       = make_float2(v[0], v[1]);
            *(float2*)(Y + (size_t)(row0 + 8) * CC + col) = make_float2(v[2], v[3]);
        }
    }
}

// ---------------------------------------------------------------------------
// Fused flash attention + gating v2.
// K/V AND pair_bias double-buffered via cp.async; mask in smem; Q fragments
// in registers. Grid (Q/64, H, B), 128 threads.
// Dynamic smem layout (floats):
//   ksm[2][64][36]  = 4608
//   vsm[2][64][40]  = 5120
//   bsm[2][64][72]  = 9216
//   qs [64][36]     = 2304
//   msk[1024]       = 1024
// total 22272 floats = 89088 B
// ---------------------------------------------------------------------------
#define AT_KS   0
#define AT_VS   (AT_KS + 2 * 64 * 36)
#define AT_BS   (AT_VS + 2 * 64 * 40)
#define AT_QS   (AT_BS + 2 * 64 * 72)
#define AT_MSK  (AT_QS + 64 * 36)
#define ATT_SMEM ((AT_MSK + 1024) * 4)

__global__ __launch_bounds__(128)
void attn_tf32(const float* __restrict__ mask_bias,
               const float* __restrict__ pair_bias)
{
    extern __shared__ float sm[];
    float* ksm = sm + AT_KS;
    float* vsm = sm + AT_VS;
    float* bsm = sm + AT_BS;
    float* qs  = sm + AT_QS;
    float* msk = sm + AT_MSK;

    const int tid  = threadIdx.x;
    const int lane = tid & 31;
    const int warp = tid >> 5;
    const int g = lane >> 2, tig = lane & 3;
    const int q0 = blockIdx.x * 64;
    const int h  = blockIdx.y;
    const int b  = blockIdx.z;
    const int wr = warp * 16;

    auto loadKVB = [&](int st, int kt) {
        // K,V: 64 rows x 8 chunks each; 4/thread each
        #pragma unroll
        for (int p = 0; p < 4; p++) {
            int ch = tid + p * 128;
            int r = ch >> 3, c = (ch & 7) * 4;
            size_t base = (size_t)(b * KLEN + kt * 64 + r) * CC + h * DD + c;
            cp16(ksm + (st * 64 + r) * 36 + c, g_kp + base);
            cp16(vsm + (st * 64 + r) * 40 + c, g_vp + base);
        }
        // pair_bias: 64 rows x 16 chunks = 1024 chunks; 8/thread
        const float* pbB = pair_bias
            + ((size_t)((b * HH + h) * QL + q0)) * KLEN + kt * 64;
        #pragma unroll
        for (int p = 0; p < 8; p++) {
            int ch = tid + p * 128;
            int r = ch >> 4, c = (ch & 15) * 4;
            cp16(bsm + (st * 64 + r) * 72 + c, pbB + (size_t)r * KLEN + c);
        }
    };

    // Prologue: Q + mask + tile 0
    #pragma unroll
    for (int p = 0; p < 4; p++) {
        int ch = tid + p * 128;
        int r = ch >> 3, c = (ch & 7) * 4;
        cp16(qs + r * 36 + c, g_qp + (size_t)(b * QL + q0 + r) * CC + h * DD + c);
    }
    #pragma unroll
    for (int p = 0; p < 2; p++) {
        int ch = tid + p * 128;
        cp16(msk + ch * 4, mask_bias + (size_t)b * KLEN + ch * 4);
    }
    loadKVB(0, 0);
    CP_COMMIT();
    CP_WAIT0();
    __syncthreads();

    // Q fragments (constant across tiles)
    unsigned aq[4][4];
    #pragma unroll
    for (int kst = 0; kst < 4; kst++) {
        aq[kst][0] = __float_as_uint(qs[(wr + g    ) * 36 + kst * 8 + tig]);
        aq[kst][1] = __float_as_uint(qs[(wr + g + 8) * 36 + kst * 8 + tig]);
        aq[kst][2] = __float_as_uint(qs[(wr + g    ) * 36 + kst * 8 + tig + 4]);
        aq[kst][3] = __float_as_uint(qs[(wr + g + 8) * 36 + kst * 8 + tig + 4]);
    }

    float m_r[2] = {-CUDART_INF_F, -CUDART_INF_F};
    float l_r[2] = {0.0f, 0.0f};
    float o[4][4] = {};

    for (int kt = 0; kt < 16; kt++) {
        const int k0 = kt * 64;
        const int cur = kt & 1;

        if (kt < 15) {
            loadKVB(cur ^ 1, kt + 1);
            CP_COMMIT();
        }

        // QK^T scores
        const float* kb = ksm + cur * 64 * 36;
        float s[8][4] = {};
        #pragma unroll
        for (int kst = 0; kst < 4; kst++) {
            #pragma unroll
            for (int nt = 0; nt < 8; nt++) {
                unsigned b0 = __float_as_uint(kb[(nt * 8 + g) * 36 + kst * 8 + tig]);
                unsigned b1 = __float_as_uint(kb[(nt * 8 + g) * 36 + kst * 8 + tig + 4]);
                mma_tf32(s[nt], aq[kst][0], aq[kst][1], aq[kst][2], aq[kst][3], b0, b1);
            }
        }

        // Biases from smem
        const float* bb = bsm + cur * 64 * 72;
        #pragma unroll
        for (int nt = 0; nt < 8; nt++) {
            int col = nt * 8 + 2 * tig;
            float2 mk = *(const float2*)(msk + k0 + col);
            float2 p0 = *(const float2*)(bb + (wr + g    ) * 72 + col);
            float2 p1 = *(const float2*)(bb + (wr + g + 8) * 72 + col);
            s[nt][0] += p0.x + mk.x;
            s[nt][1] += p0.y + mk.y;
            s[nt][2] += p1.x + mk.x;
            s[nt][3] += p1.y + mk.y;
        }

        // Online softmax (rows g, g+8)
        float rm0 = -CUDART_INF_F, rm1 = -CUDART_INF_F;
        #pragma unroll
        for (int nt = 0; nt < 8; nt++) {
            rm0 = fmaxf(rm0, fmaxf(s[nt][0], s[nt][1]));
            rm1 = fmaxf(rm1, fmaxf(s[nt][2], s[nt][3]));
        }
        rm0 = fmaxf(rm0, __shfl_xor_sync(0xffffffffu, rm0, 1));
        rm0 = fmaxf(rm0, __shfl_xor_sync(0xffffffffu, rm0, 2));
        rm1 = fmaxf(rm1, __shfl_xor_sync(0xffffffffu, rm1, 1));
        rm1 = fmaxf(rm1, __shfl_xor_sync(0xffffffffu, rm1, 2));
        float mn0 = fmaxf(m_r[0], rm0);
        float mn1 = fmaxf(m_r[1], rm1);

        float rs0 = 0.0f, rs1 = 0.0f;
        #pragma unroll
        for (int nt = 0; nt < 8; nt++) {
            s[nt][0] = __expf(s[nt][0] - mn0);
            s[nt][1] = __expf(s[nt][1] - mn0);
            s[nt][2] = __expf(s[nt][2] - mn1);
            s[nt][3] = __expf(s[nt][3] - mn1);
            rs0 += s[nt][0] + s[nt][1];
            rs1 += s[nt][2] + s[nt][3];
        }
        rs0 += __shfl_xor_sync(0xffffffffu, rs0, 1);
        rs0 += __shfl_xor_sync(0xffffffffu, rs0, 2);
        rs1 += __shfl_xor_sync(0xffffffffu, rs1, 1);
        rs1 += __shfl_xor_sync(0xffffffffu, rs1, 2);

        float f0 = __expf(m_r[0] - mn0);
        float f1 = __expf(m_r[1] - mn1);
        l_r[0] = l_r[0] * f0 + rs0;  m_r[0] = mn0;
        l_r[1] = l_r[1] * f1 + rs1;  m_r[1] = mn1;

        #pragma unroll
        for (int nt = 0; nt < 4; nt++) {
            o[nt][0] *= f0; o[nt][1] *= f0;
            o[nt][2] *= f1; o[nt][3] *= f1;
        }

        // AV: P (C-layout) -> A-fragments via quad shuffles
        const float* vb = vsm + cur * 64 * 40;
        #pragma unroll
        for (int kst = 0; kst < 8; kst++) {
            int src0 = (lane & ~3) | (tig >> 1);
            int src1 = src0 + 2;
            float e0 = __shfl_sync(0xffffffffu, s[kst][0], src0);
            float e1 = __shfl_sync(0xffffffffu, s[kst][1], src0);
            float e2 = __shfl_sync(0xffffffffu, s[kst][2], src0);
            float e3 = __shfl_sync(0xffffffffu, s[kst][3], src0);
            float h0 = __shfl_sync(0xffffffffu, s[kst][0], src1);
            float h1 = __shfl_sync(0xffffffffu, s[kst][1], src1);
            float h2 = __shfl_sync(0xffffffffu, s[kst][2], src1);
            float h3 = __shfl_sync(0xffffffffu, s[kst][3], src1);
            bool odd = (tig & 1);
            unsigned a0 = f2tf(odd ? e1 : e0);
            unsigned a1 = f2tf(odd ? e3 : e2);
            unsigned a2 = f2tf(odd ? h1 : h0);
            unsigned a3 = f2tf(odd ? h3 : h2);
            #pragma unroll
            for (int nt = 0; nt < 4; nt++) {
                unsigned b0 = __float_as_uint(vb[(kst * 8 + tig    ) * 40 + nt * 8 + g]);
                unsigned b1 = __float_as_uint(vb[(kst * 8 + tig + 4) * 40 + nt * 8 + g]);
                mma_tf32(o[nt], a0, a1, a2, a3, b0, b1);
            }
        }

        if (kt < 15) { CP_WAIT0(); }
        __syncthreads();
    }

    // Epilogue: normalize, gate, write g_o as tf32 bit patterns
    float invl0 = 1.0f / l_r[0];
    float invl1 = 1.0f / l_r[1];
    #pragma unroll
    for (int nt = 0; nt < 4; nt++) {
        int col = nt * 8 + 2 * tig;
        size_t base0 = (size_t)(b * QL + q0 + wr + g) * CC + h * DD + col;
        size_t base1 = base0 + 8 * (size_t)CC;
        float2 ga = *(const float2*)(g_gp + base0);
        float2 gb = *(const float2*)(g_gp + base1);
        float2 w0 = make_float2(__uint_as_float(f2tf(o[nt][0] * invl0 * ga.x)),
                                __uint_as_float(f2tf(o[nt][1] * invl0 * ga.y)));
        float2 w1 = make_float2(__uint_as_float(f2tf(o[nt][2] * invl1 * gb.x)),
                                __uint_as_float(f2tf(o[nt][3] * invl1 * gb.y)));
        *(float2*)(g_o + base0) = w0;
        *(float2*)(g_o + base1) = w1;
    }
}

// ---------------------------------------------------------------------------
extern "C" void kernel_launch(void* const* d_in, const int* in_sizes, int n_in,
                              void* d_out, int out_size)
{
    (void)in_sizes; (void)n_in; (void)out_size;
    const float* q_x       = (const float*)d_in[0];
    const float* kv_x      = (const float*)d_in[1];
    const float* mask_bias = (const float*)d_in[2];
    const float* pair_bias = (const float*)d_in[3];
    const float* wq        = (const float*)d_in[4];
    const float* wk        = (const float*)d_in[5];
    const float* wv        = (const float*)d_in[6];
    const float* wg        = (const float*)d_in[7];
    const float* bg        = (const float*)d_in[8];
    const float* wo        = (const float*)d_in[9];
    const float* bo        = (const float*)d_in[10];
    float* out = (float*)d_out;

    static bool attr_done = false;
    if (!attr_done) {
        cudaFuncSetAttribute(gemm_tf32, cudaFuncAttributeMaxDynamicSharedMemorySize, GEMM_SMEM);
        cudaFuncSetAttribute(attn_tf32, cudaFuncAttributeMaxDynamicSharedMemorySize, ATT_SMEM);
        attr_done = true;
    }

    prep_tf32<<<dim3(1024, 3), 256>>>(q_x, kv_x, wq, wk, wv, wg, wo);

    gemm_tf32<<<dim3(MM / 64, CC / 128, 4), 256, GEMM_SMEM>>>(bg, bo, nullptr, 0);

    attn_tf32<<<dim3(QL / 64, HH, BB), 128, ATT_SMEM>>>(mask_bias, pair_bias);

    gemm_tf32<<<dim3(MM / 64, CC / 128, 1), 256, GEMM_SMEM>>>(bg, bo, out, 4);
}

// round 5
// speedup vs baseline: 3.4522x; 1.3578x over previous
#include <cuda_runtime.h>
#include <cuda_fp16.h>
#include <math_constants.h>

#define BB 4
#define QL 1024
#define KLEN 1024
#define CC 256
#define HH 8
#define DD 32
#define MM (BB * QL)

// Scratch device globals (no allocation allowed)
__device__ __half g_xq [MM * CC];      // fp16(q_x)
__device__ __half g_xkv[MM * CC];      // fp16(kv_x)
__device__ __half g_wts[5 * CC * CC];  // fp16(wq,wk,wv,wg,wo)
__device__ __half g_qp[MM * CC];       // fp16(q/sqrt(D))  [b*Q+q][h*D+d]
__device__ __half g_kp[MM * CC];       // fp16(k)
__device__ __half g_vt[MM * CC];       // fp16(v) TRANSPOSED: [(b*H+h)*D+d][tok]
__device__ float  g_gp[MM * CC];       // sigmoid gate (fp32)
__device__ __half g_o [MM * CC];       // fp16(gated attention out)

__device__ __forceinline__ unsigned packh2(float lo, float hi) {
    __half2 h = __floats2half2_rn(lo, hi);
    return *reinterpret_cast<unsigned*>(&h);
}

__device__ __forceinline__ void mma_f16(float c[4],
                                        unsigned a0, unsigned a1, unsigned a2, unsigned a3,
                                        unsigned b0, unsigned b1) {
    asm volatile(
        "mma.sync.aligned.m16n8k16.row.col.f32.f16.f16.f32 "
        "{%0,%1,%2,%3}, {%4,%5,%6,%7}, {%8,%9}, {%0,%1,%2,%3};"
        : "+f"(c[0]), "+f"(c[1]), "+f"(c[2]), "+f"(c[3])
        : "r"(a0), "r"(a1), "r"(a2), "r"(a3), "r"(b0), "r"(b1));
}

__device__ __forceinline__ void cp16(void* dst_smem, const void* src) {
    unsigned d = (unsigned)__cvta_generic_to_shared(dst_smem);
    asm volatile("cp.async.cg.shared.global [%0], [%1], 16;" :: "r"(d), "l"(src));
}
#define CP_COMMIT() asm volatile("cp.async.commit_group;")
#define CP_WAIT0()  asm volatile("cp.async.wait_group 0;")
#define CP_WAIT1()  asm volatile("cp.async.wait_group 1;")
#define CP_WAIT2()  asm volatile("cp.async.wait_group 2;")

// ---------------------------------------------------------------------------
// Prep: fp16-convert q_x, kv_x, five weight matrices. Grid (1024,3) x 256.
// ---------------------------------------------------------------------------
__global__ __launch_bounds__(256)
void prep_f16(const float* __restrict__ qx, const float* __restrict__ kvx,
              const float* __restrict__ wq, const float* __restrict__ wk,
              const float* __restrict__ wv, const float* __restrict__ wg,
              const float* __restrict__ wo)
{
    const int seg = blockIdx.y;
    const int i4 = blockIdx.x * 256 + threadIdx.x;
    const float* src; __half* dst; int idx = i4;
    if (seg == 0)      { src = qx;  dst = g_xq;  }
    else if (seg == 1) { src = kvx; dst = g_xkv; }
    else {
        if (i4 >= 5 * CC * CC / 4) return;
        int w = i4 / (CC * CC / 4);
        idx = i4 - w * (CC * CC / 4);
        const float* ws[5] = {wq, wk, wv, wg, wo};
        src = ws[w];
        dst = g_wts + (size_t)w * CC * CC;
    }
    float4 v = ((const float4*)src)[idx];
    uint2 u;
    u.x = packh2(v.x, v.y);
    u.y = packh2(v.z, v.w);
    ((uint2*)dst)[idx] = u;
}

// ---------------------------------------------------------------------------
// fp16 GEMM: Y[m][n] = sum_k X[m][k]*W[n][k]; M=4096 N=256 K=256.
// BM=64 BN=64 BK=32; 256 thr = 8 warps (2 m x 4 n, warp tile 32x16).
// 3-stage cp.async pipeline. modes: 0 q 1 k 2 v(transposed out) 3 gate 4 out.
// ---------------------------------------------------------------------------
#define G_STAGE (64 * 40)                       // halves per operand stage
#define GEMM_SMEM (3 * 2 * G_STAGE * 2)         // 30720 B

__global__ __launch_bounds__(256)
void gemm_f16(const float* __restrict__ bg, const float* __restrict__ bo,
              float* __restrict__ outp, int mode_base)
{
    extern __shared__ __half smh[];
    __half* As = smh;                  // [3][64][40]
    __half* Bs = smh + 3 * G_STAGE;    // [3][64][40]

    const int mode = mode_base + blockIdx.z;
    const __half* X; const __half* W; const float* bias = nullptr;
    switch (mode) {
        case 0:  X = g_xq;  W = g_wts;               break;
        case 1:  X = g_xkv; W = g_wts + 1 * CC * CC; break;
        case 2:  X = g_xkv; W = g_wts + 2 * CC * CC; break;
        case 3:  X = g_xq;  W = g_wts + 3 * CC * CC; bias = bg; break;
        default: X = g_o;   W = g_wts + 4 * CC * CC; bias = bo; break;
    }

    const int tid  = threadIdx.x;
    const int lane = tid & 31;
    const int warp = tid >> 5;
    const int wm = warp & 1;
    const int wn = warp >> 1;
    const int g = lane >> 2, tig = lane & 3;
    const int m0 = blockIdx.x * 64;
    const int n0 = blockIdx.y * 64;

    const int r = tid >> 2;            // 0..63
    const int c = (tid & 3) * 8;       // 0..24

    auto loadTiles = [&](int st, int kk) {
        cp16(As + (st * 64 + r) * 40 + c, X + (size_t)(m0 + r) * CC + kk + c);
        cp16(Bs + (st * 64 + r) * 40 + c, W + (size_t)(n0 + r) * CC + kk + c);
    };

    float acc[2][2][4] = {};

    loadTiles(0, 0);  CP_COMMIT();
    loadTiles(1, 32); CP_COMMIT();

    for (int kt = 0; kt < 8; kt++) {
        const int st = kt % 3;
        if (kt + 2 < 8) {
            loadTiles((kt + 2) % 3, (kt + 2) * 32);
            CP_COMMIT();
            CP_WAIT2();
        } else if (kt == 6) {
            CP_WAIT1();
        } else {
            CP_WAIT0();
        }
        __syncthreads();

        const __half* Ab = As + st * G_STAGE;
        const __half* Bb = Bs + st * G_STAGE;
        #pragma unroll
        for (int kst = 0; kst < 2; kst++) {
            unsigned a[2][4];
            #pragma unroll
            for (int mt = 0; mt < 2; mt++) {
                int row = wm * 32 + mt * 16;
                a[mt][0] = *(const unsigned*)(Ab + (row + g    ) * 40 + kst * 16 + 2 * tig);
                a[mt][1] = *(const unsigned*)(Ab + (row + g + 8) * 40 + kst * 16 + 2 * tig);
                a[mt][2] = *(const unsigned*)(Ab + (row + g    ) * 40 + kst * 16 + 2 * tig + 8);
                a[mt][3] = *(const unsigned*)(Ab + (row + g + 8) * 40 + kst * 16 + 2 * tig + 8);
            }
            #pragma unroll
            for (int nt = 0; nt < 2; nt++) {
                int n = wn * 16 + nt * 8;
                unsigned b0 = *(const unsigned*)(Bb + (n + g) * 40 + kst * 16 + 2 * tig);
                unsigned b1 = *(const unsigned*)(Bb + (n + g) * 40 + kst * 16 + 2 * tig + 8);
                mma_f16(acc[0][nt], a[0][0], a[0][1], a[0][2], a[0][3], b0, b1);
                mma_f16(acc[1][nt], a[1][0], a[1][1], a[1][2], a[1][3], b0, b1);
            }
        }
        __syncthreads();
    }

    // Epilogue
    #pragma unroll
    for (int mt = 0; mt < 2; mt++) {
        int row0 = m0 + wm * 32 + mt * 16 + g;
        #pragma unroll
        for (int nt = 0; nt < 2; nt++) {
            int col = n0 + wn * 16 + nt * 8 + 2 * tig;
            float v[4] = {acc[mt][nt][0], acc[mt][nt][1], acc[mt][nt][2], acc[mt][nt][3]};
            if (mode == 0) {
                #pragma unroll
                for (int u = 0; u < 4; u++) v[u] *= 0.17677669529663689f;
            } else if (mode == 3) {
                float b0v = bias[col], b1v = bias[col + 1];
                v[0] = 1.0f / (1.0f + __expf(-(v[0] + b0v)));
                v[1] = 1.0f / (1.0f + __expf(-(v[1] + b1v)));
                v[2] = 1.0f / (1.0f + __expf(-(v[2] + b0v)));
                v[3] = 1.0f / (1.0f + __expf(-(v[3] + b1v)));
            } else if (mode == 4) {
                float b0v = bias[col], b1v = bias[col + 1];
                v[0] += b0v; v[1] += b1v; v[2] += b0v; v[3] += b1v;
            }
            if (mode == 2) {
                // transposed scatter: g_vt[(b*H+h)*D+d][tok]
                int bidx = row0 >> 10, tok = row0 & 1023;
                int hh = col >> 5, dd = col & 31;
                size_t base = ((size_t)(bidx * HH + hh) * DD + dd) * KLEN + tok;
                g_vt[base]            = __float2half_rn(v[0]);
                g_vt[base + KLEN]     = __float2half_rn(v[1]);   // d+1
                g_vt[base + 8]        = __float2half_rn(v[2]);   // tok+8
                g_vt[base + KLEN + 8] = __float2half_rn(v[3]);
            } else if (mode == 0 || mode == 1) {
                __half* Y = (mode == 0) ? g_qp : g_kp;
                *(__half2*)(Y + (size_t)row0 * CC + col) = __floats2half2_rn(v[0], v[1]);
                *(__half2*)(Y + (size_t)(row0 + 8) * CC + col) = __floats2half2_rn(v[2], v[3]);
            } else if (mode == 3) {
                *(float2*)(g_gp + (size_t)row0 * CC + col)       = make_float2(v[0], v[1]);
                *(float2*)(g_gp + (size_t)(row0 + 8) * CC + col) = make_float2(v[2], v[3]);
            } else {
                *(float2*)(outp + (size_t)row0 * CC + col)       = make_float2(v[0], v[1]);
                *(float2*)(outp + (size_t)(row0 + 8) * CC + col) = make_float2(v[2], v[3]);
            }
        }
    }
}

// ---------------------------------------------------------------------------
// Fused flash attention + gating, fp16 mma. Grid (Q/64, H, B), 128 threads.
// smem (bytes): ks[2][64][40]h=10240, vt[2][32][72]h=9216,
//               bias[2][64][76]f=38912, qs[64][40]h=5120, msk[1024]f=4096
// ---------------------------------------------------------------------------
#define AT_KS   0
#define AT_VT   10240
#define AT_BS   19456
#define AT_QS   58368
#define AT_MSK  63488
#define ATT_SMEM 67584

__global__ __launch_bounds__(128)
void attn_f16(const float* __restrict__ mask_bias,
              const float* __restrict__ pair_bias)
{
    extern __shared__ char smc[];
    __half* ks  = (__half*)(smc + AT_KS);
    __half* vt  = (__half*)(smc + AT_VT);
    float*  bsm = (float*)(smc + AT_BS);
    __half* qs  = (__half*)(smc + AT_QS);
    float*  msk = (float*)(smc + AT_MSK);

    const int tid  = threadIdx.x;
    const int lane = tid & 31;
    const int warp = tid >> 5;
    const int g = lane >> 2, tig = lane & 3;
    const int q0 = blockIdx.x * 64;
    const int h  = blockIdx.y;
    const int b  = blockIdx.z;
    const int wr = warp * 16;

    auto loadKVB = [&](int st, int kt) {
        // K: 64 rows x 4 chunks = 256; 2/thread
        #pragma unroll
        for (int p = 0; p < 2; p++) {
            int ch = tid + p * 128;
            int r = ch >> 2, c = (ch & 3) * 8;
            cp16(ks + (st * 64 + r) * 40 + c,
                 g_kp + (size_t)(b * KLEN + kt * 64 + r) * CC + h * DD + c);
        }
        // Vt: 32 rows x 8 chunks = 256; 2/thread
        #pragma unroll
        for (int p = 0; p < 2; p++) {
            int ch = tid + p * 128;
            int r = ch >> 3, c = (ch & 7) * 8;
            cp16(vt + (st * 32 + r) * 72 + c,
                 g_vt + ((size_t)(b * HH + h) * DD + r) * KLEN + kt * 64 + c);
        }
        // pair_bias: 64 rows x 16 chunks = 1024; 8/thread
        const float* pbB = pair_bias
            + ((size_t)((b * HH + h) * QL + q0)) * KLEN + kt * 64;
        #pragma unroll
        for (int p = 0; p < 8; p++) {
            int ch = tid + p * 128;
            int r = ch >> 4, c = (ch & 15) * 4;
            cp16(bsm + (st * 64 + r) * 76 + c, pbB + (size_t)r * KLEN + c);
        }
    };

    // Prologue: Q + mask + tile 0
    #pragma unroll
    for (int p = 0; p < 2; p++) {
        int ch = tid + p * 128;
        int r = ch >> 2, c = (ch & 3) * 8;
        cp16(qs + r * 40 + c, g_qp + (size_t)(b * QL + q0 + r) * CC + h * DD + c);
    }
    #pragma unroll
    for (int p = 0; p < 2; p++) {
        int ch = tid + p * 128;
        cp16(msk + ch * 4, mask_bias + (size_t)b * KLEN + ch * 4);
    }
    loadKVB(0, 0);
    CP_COMMIT();
    CP_WAIT0();
    __syncthreads();

    // Q fragments (constant across tiles)
    unsigned aq[2][4];
    #pragma unroll
    for (int kst = 0; kst < 2; kst++) {
        aq[kst][0] = *(const unsigned*)(qs + (wr + g    ) * 40 + kst * 16 + 2 * tig);
        aq[kst][1] = *(const unsigned*)(qs + (wr + g + 8) * 40 + kst * 16 + 2 * tig);
        aq[kst][2] = *(const unsigned*)(qs + (wr + g    ) * 40 + kst * 16 + 2 * tig + 8);
        aq[kst][3] = *(const unsigned*)(qs + (wr + g + 8) * 40 + kst * 16 + 2 * tig + 8);
    }

    float m_r[2] = {-CUDART_INF_F, -CUDART_INF_F};
    float l_r[2] = {0.0f, 0.0f};
    float o[4][4] = {};

    for (int kt = 0; kt < 16; kt++) {
        const int k0 = kt * 64;
        const int cur = kt & 1;

        if (kt < 15) {
            loadKVB(cur ^ 1, kt + 1);
            CP_COMMIT();
        }

        // QK^T
        const __half* kb = ks + cur * 64 * 40;
        float s[8][4] = {};
        #pragma unroll
        for (int nt = 0; nt < 8; nt++) {
            #pragma unroll
            for (int kst = 0; kst < 2; kst++) {
                unsigned b0 = *(const unsigned*)(kb + (nt * 8 + g) * 40 + kst * 16 + 2 * tig);
                unsigned b1 = *(const unsigned*)(kb + (nt * 8 + g) * 40 + kst * 16 + 2 * tig + 8);
                mma_f16(s[nt], aq[kst][0], aq[kst][1], aq[kst][2], aq[kst][3], b0, b1);
            }
        }

        // biases
        const float* bb = bsm + cur * 64 * 76;
        #pragma unroll
        for (int nt = 0; nt < 8; nt++) {
            int col = nt * 8 + 2 * tig;
            float2 mk = *(const float2*)(msk + k0 + col);
            float2 p0 = *(const float2*)(bb + (wr + g    ) * 76 + col);
            float2 p1 = *(const float2*)(bb + (wr + g + 8) * 76 + col);
            s[nt][0] += p0.x + mk.x;
            s[nt][1] += p0.y + mk.y;
            s[nt][2] += p1.x + mk.x;
            s[nt][3] += p1.y + mk.y;
        }

        // online softmax (rows g, g+8)
        float rm0 = -CUDART_INF_F, rm1 = -CUDART_INF_F;
        #pragma unroll
        for (int nt = 0; nt < 8; nt++) {
            rm0 = fmaxf(rm0, fmaxf(s[nt][0], s[nt][1]));
            rm1 = fmaxf(rm1, fmaxf(s[nt][2], s[nt][3]));
        }
        rm0 = fmaxf(rm0, __shfl_xor_sync(0xffffffffu, rm0, 1));
        rm0 = fmaxf(rm0, __shfl_xor_sync(0xffffffffu, rm0, 2));
        rm1 = fmaxf(rm1, __shfl_xor_sync(0xffffffffu, rm1, 1));
        rm1 = fmaxf(rm1, __shfl_xor_sync(0xffffffffu, rm1, 2));
        float mn0 = fmaxf(m_r[0], rm0);
        float mn1 = fmaxf(m_r[1], rm1);

        float rs0 = 0.0f, rs1 = 0.0f;
        #pragma unroll
        for (int nt = 0; nt < 8; nt++) {
            s[nt][0] = __expf(s[nt][0] - mn0);
            s[nt][1] = __expf(s[nt][1] - mn0);
            s[nt][2] = __expf(s[nt][2] - mn1);
            s[nt][3] = __expf(s[nt][3] - mn1);
            rs0 += s[nt][0] + s[nt][1];
            rs1 += s[nt][2] + s[nt][3];
        }
        rs0 += __shfl_xor_sync(0xffffffffu, rs0, 1);
        rs0 += __shfl_xor_sync(0xffffffffu, rs0, 2);
        rs1 += __shfl_xor_sync(0xffffffffu, rs1, 1);
        rs1 += __shfl_xor_sync(0xffffffffu, rs1, 2);

        float f0 = __expf(m_r[0] - mn0);
        float f1 = __expf(m_r[1] - mn1);
        l_r[0] = l_r[0] * f0 + rs0;  m_r[0] = mn0;
        l_r[1] = l_r[1] * f1 + rs1;  m_r[1] = mn1;

        #pragma unroll
        for (int nt = 0; nt < 4; nt++) {
            o[nt][0] *= f0; o[nt][1] *= f0;
            o[nt][2] *= f1; o[nt][3] *= f1;
        }

        // AV: C-fragments pack directly into fp16 A-fragments (no shuffles)
        const __half* vb = vt + cur * 32 * 72;
        #pragma unroll
        for (int kst = 0; kst < 4; kst++) {
            unsigned a0 = packh2(s[2 * kst    ][0], s[2 * kst    ][1]);
            unsigned a1 = packh2(s[2 * kst    ][2], s[2 * kst    ][3]);
            unsigned a2 = packh2(s[2 * kst + 1][0], s[2 * kst + 1][1]);
            unsigned a3 = packh2(s[2 * kst + 1][2], s[2 * kst + 1][3]);
            #pragma unroll
            for (int nt = 0; nt < 4; nt++) {
                unsigned b0 = *(const unsigned*)(vb + (nt * 8 + g) * 72 + kst * 16 + 2 * tig);
                unsigned b1 = *(const unsigned*)(vb + (nt * 8 + g) * 72 + kst * 16 + 2 * tig + 8);
                mma_f16(o[nt], a0, a1, a2, a3, b0, b1);
            }
        }

        if (kt < 15) { CP_WAIT0(); }
        __syncthreads();
    }

    // Epilogue: normalize, gate, write g_o (fp16)
    float invl0 = 1.0f / l_r[0];
    float invl1 = 1.0f / l_r[1];
    #pragma unroll
    for (int nt = 0; nt < 4; nt++) {
        int col = nt * 8 + 2 * tig;
        size_t base0 = (size_t)(b * QL + q0 + wr + g) * CC + h * DD + col;
        size_t base1 = base0 + 8 * (size_t)CC;
        float2 ga = *(const float2*)(g_gp + base0);
        float2 gb = *(const float2*)(g_gp + base1);
        *(__half2*)(g_o + base0) = __floats2half2_rn(o[nt][0] * invl0 * ga.x,
                                                     o[nt][1] * invl0 * ga.y);
        *(__half2*)(g_o + base1) = __floats2half2_rn(o[nt][2] * invl1 * gb.x,
                                                     o[nt][3] * invl1 * gb.y);
    }
}

// ---------------------------------------------------------------------------
extern "C" void kernel_launch(void* const* d_in, const int* in_sizes, int n_in,
                              void* d_out, int out_size)
{
    (void)in_sizes; (void)n_in; (void)out_size;
    const float* q_x       = (const float*)d_in[0];
    const float* kv_x      = (const float*)d_in[1];
    const float* mask_bias = (const float*)d_in[2];
    const float* pair_bias = (const float*)d_in[3];
    const float* wq        = (const float*)d_in[4];
    const float* wk        = (const float*)d_in[5];
    const float* wv        = (const float*)d_in[6];
    const float* wg        = (const float*)d_in[7];
    const float* bg        = (const float*)d_in[8];
    const float* wo        = (const float*)d_in[9];
    const float* bo        = (const float*)d_in[10];
    float* out = (float*)d_out;

    static bool attr_done = false;
    if (!attr_done) {
        cudaFuncSetAttribute(gemm_f16, cudaFuncAttributeMaxDynamicSharedMemorySize, GEMM_SMEM);
        cudaFuncSetAttribute(attn_f16, cudaFuncAttributeMaxDynamicSharedMemorySize, ATT_SMEM);
        attr_done = true;
    }

    prep_f16<<<dim3(1024, 3), 256>>>(q_x, kv_x, wq, wk, wv, wg, wo);

    gemm_f16<<<dim3(MM / 64, CC / 64, 4), 256, GEMM_SMEM>>>(bg, bo, nullptr, 0);

    attn_f16<<<dim3(QL / 64, HH, BB), 128, ATT_SMEM>>>(mask_bias, pair_bias);

    gemm_f16<<<dim3(MM / 64, CC / 64, 1), 256, GEMM_SMEM>>>(bg, bo, out, 4);
}